// round 11
// baseline (speedup 1.0000x reference)
#include <cuda_runtime.h>
#include <cuda_bf16.h>
#include <cuda_fp16.h>
#include <cstdint>

// ---------------- Problem constants ----------------
#define B_     16384
#define F_     26
#define V_     100000
#define E_     16
#define CONT_  13
#define K1_    429     // CONT_ + F_*E_
#define KP1_   448     // dnn_in K padded (mult of 64)
#define KP2_   416     // h1 K padded (mult of 32)
#define H_     400
#define NT_    80      // CTA N tile (5 * 80 = 400, exact)
#define MT_    256     // CTA M tile

// dnn_in layout (KP1_): [ emb 0..415 | cont 416..428 | zero 429..447 ]
// h1 layout (KP2_):     [ h1 0..399 | zero 400..415 ]  (pad never written)

// ---------------- Scratch (device globals) ----------------
__device__ __align__(256) __half g_dnn [(size_t)B_ * KP1_];
__device__ __align__(256) __half g_h1  [(size_t)B_ * KP2_];
__device__ __align__(256) __half g_w1t [(size_t)H_ * KP1_];
__device__ __align__(256) __half g_w2t [(size_t)H_ * KP2_];
__device__ float g_fm  [B_];
__device__ float g_part[5][B_];
__device__ int   g_cnt [B_ / MT_];      // zero-init; self-resetting

// ---------------- PTX helpers ----------------
__device__ __forceinline__ uint32_t smem_u32(const void* p) {
    return (uint32_t)__cvta_generic_to_shared(p);
}
#define CP16(dst_u32, src) \
    asm volatile("cp.async.cg.shared.global [%0], [%1], 16;" :: "r"(dst_u32), "l"(src))
#define CP_COMMIT() asm volatile("cp.async.commit_group;" ::: "memory")
#define CP_WAIT0()  asm volatile("cp.async.wait_group 0;" ::: "memory")
#define CP_WAIT1()  asm volatile("cp.async.wait_group 1;" ::: "memory")

#define LDSM_X4(r0, r1, r2, r3, addr)                                          \
    asm volatile("ldmatrix.sync.aligned.m8n8.x4.shared.b16 {%0,%1,%2,%3},[%4];"\
                 : "=r"(r0), "=r"(r1), "=r"(r2), "=r"(r3) : "r"(addr))
#define LDSM_X2(r0, r1, addr)                                                  \
    asm volatile("ldmatrix.sync.aligned.m8n8.x2.shared.b16 {%0,%1},[%2];"      \
                 : "=r"(r0), "=r"(r1) : "r"(addr))

__device__ __forceinline__ void mma_fp16(float* c,
                                         uint32_t a0, uint32_t a1, uint32_t a2, uint32_t a3,
                                         uint32_t b0, uint32_t b1) {
    asm volatile(
        "mma.sync.aligned.m16n8k16.row.col.f32.f16.f16.f32 "
        "{%0,%1,%2,%3},{%4,%5,%6,%7},{%8,%9},{%0,%1,%2,%3};"
        : "+f"(c[0]), "+f"(c[1]), "+f"(c[2]), "+f"(c[3])
        : "r"(a0), "r"(a1), "r"(a2), "r"(a3), "r"(b0), "r"(b1));
}

// ============================================================================
// Kernel 1 (merged): blocks [0, 2048): gather + FM (one warp per sample);
//                    blocks [2048, 2748): weight prep.
// ============================================================================
#define GATHER_BLKS (B_ / 8)     // 2048
#define PREP_BLKS   700          // ceil(400*448 / 256)

__global__ void gather_prep_kernel(const float* __restrict__ cont,
                                   const int*   __restrict__ cat,
                                   const float* __restrict__ w_cont,
                                   const float* __restrict__ b_cont,
                                   const float* __restrict__ t_first,
                                   const float* __restrict__ t_emb,
                                   const float* __restrict__ W1,
                                   const float* __restrict__ W2) {
    if (blockIdx.x >= GATHER_BLKS) {
        int idx = (blockIdx.x - GATHER_BLKS) * 256 + threadIdx.x;
        if (idx < H_ * KP1_) {               // W1T: [400][448] in dnn layout
            int n = idx / KP1_, k = idx % KP1_;
            float v;
            if (k < 416)      v = W1[(size_t)(CONT_ + k) * H_ + n];
            else if (k < 429) v = W1[(size_t)(k - 416) * H_ + n];
            else              v = 0.f;
            g_w1t[idx] = __float2half_rn(v);
        }
        if (idx < H_ * KP2_) {               // W2T: [400][416]
            int n = idx / KP2_, k = idx % KP2_;
            float v = (k < H_) ? W2[(size_t)k * H_ + n] : 0.f;
            g_w2t[idx] = __float2half_rn(v);
        }
        return;
    }

    int warp = (blockIdx.x * blockDim.x + threadIdx.x) >> 5;
    int lane = threadIdx.x & 31;
    const int b = warp;

    float v[16];
    #pragma unroll
    for (int i = 0; i < 16; i++) v[i] = 0.f;
    float q = 0.f, scal = 0.f;

    if (lane < F_) {
        int idx = cat[b * F_ + lane];
        const float4* row =
            reinterpret_cast<const float4*>(t_emb + ((size_t)lane * V_ + (size_t)idx) * E_);
        float4 r0 = row[0], r1 = row[1], r2 = row[2], r3 = row[3];
        v[0]=r0.x; v[1]=r0.y; v[2]=r0.z; v[3]=r0.w;
        v[4]=r1.x; v[5]=r1.y; v[6]=r1.z; v[7]=r1.w;
        v[8]=r2.x; v[9]=r2.y; v[10]=r2.z; v[11]=r2.w;
        v[12]=r3.x; v[13]=r3.y; v[14]=r3.z; v[15]=r3.w;

        uint32_t pk[8];
        #pragma unroll
        for (int i = 0; i < 8; i++) {
            __half h0 = __float2half_rn(v[2*i]);
            __half h1 = __float2half_rn(v[2*i+1]);
            pk[i] = (uint32_t)__half_as_ushort(h0) | ((uint32_t)__half_as_ushort(h1) << 16);
            q = fmaf(v[2*i],   v[2*i],   q);
            q = fmaf(v[2*i+1], v[2*i+1], q);
        }
        uint4* dst = reinterpret_cast<uint4*>(g_dnn + (size_t)b * KP1_ + lane * E_);
        dst[0] = make_uint4(pk[0], pk[1], pk[2], pk[3]);
        dst[1] = make_uint4(pk[4], pk[5], pk[6], pk[7]);
        scal = t_first[(size_t)lane * V_ + (size_t)idx];
    }
    if (lane < CONT_) {
        float c = cont[b * CONT_ + lane];
        g_dnn[(size_t)b * KP1_ + 416 + lane] = __float2half_rn(c);
        scal = fmaf(c, w_cont[lane], scal);
    }
    if (lane < KP1_ - K1_) {     // zero cols 429..447 (19 lanes)
        g_dnn[(size_t)b * KP1_ + K1_ + lane] = __ushort_as_half((unsigned short)0);
    }

    #pragma unroll
    for (int off = 16; off; off >>= 1) {
        #pragma unroll
        for (int e = 0; e < 16; e++)
            v[e] += __shfl_xor_sync(0xffffffffu, v[e], off);
        q    += __shfl_xor_sync(0xffffffffu, q,    off);
        scal += __shfl_xor_sync(0xffffffffu, scal, off);
    }
    if (lane == 0) {
        float ss = 0.f;
        #pragma unroll
        for (int e = 0; e < 16; e++) ss = fmaf(v[e], v[e], ss);
        g_fm[b] = scal + b_cont[0] + 0.5f * (ss - q);
    }
}

// ============================================================================
// fp16 GEMM via mma.sync m16n8k16. CTA 256(M) x 80(N), 8 warps (4M x 2N),
//   warp tile 64x40, 256 threads. Template BK (32/64), double-buffered.
//   SMEM rows ROWB = 2*BK+16 -> conflict-free ldmatrix.
//   FUSE=0: relu(+bias) -> C fp16.
//   FUSE=1: fused dot w/ Wout -> g_part; last CTA per M-tile sums + writes out.
// ============================================================================
template<int BK, bool FUSE>
__global__ void __launch_bounds__(256, 2)
gemm_fp16(const __half* __restrict__ A,
          const __half* __restrict__ Bh,
          int ldk, int NKB,
          const float* __restrict__ bias,    // [H_]
          const float* __restrict__ Wout,    // [1+H_] (FUSE)
          const float* __restrict__ bout,    // [1]    (FUSE)
          float* __restrict__ out,           // [B_]   (FUSE)
          __half* __restrict__ C, int ldc) { // (!FUSE)
    constexpr int ROWB  = 2 * BK + 16;
    constexpr int CPR   = BK / 8;            // 16B chunks per row
    constexpr int OFFB  = MT_ * ROWB;
    constexpr int STAGE = (MT_ + NT_) * ROWB;
    constexpr int NCH   = (MT_ + NT_) * CPR;
    constexpr int NIT   = (NCH + 255) / 256;

    extern __shared__ char smem_raw[];
    __shared__ float part[2][MT_];
    __shared__ int   s_done;
    const uint32_t sbase = smem_u32(smem_raw);

    const int tid  = threadIdx.x;
    const int warp = tid >> 5, lane = tid & 31;
    const int gr = lane >> 2, gc = lane & 3;
    const int wm  = (warp >> 1) * 64;    // warp row band (0/64/128/192)
    const int wni = warp & 1;
    const int wn  = wni * 40;            // warp col band (0 / 40)
    const int m0 = blockIdx.y * MT_;
    const int n0 = blockIdx.x * NT_;

    const int lane8 = lane & 7;
    const int laneH = (lane >> 3) & 1;
    const int laneK = lane >> 4;
    const uint32_t aoff  = (uint32_t)((wm + lane8 + laneH * 8) * ROWB + laneK * 16);
    const uint32_t boff4 = (uint32_t)((wn + lane8 + laneK * 8) * ROWB + laneH * 16);
    const uint32_t boff2 = (uint32_t)((wn + 32 + lane8) * ROWB + laneH * 16);

    float acc[4][5][4];
    #pragma unroll
    for (int i = 0; i < 4; i++)
        #pragma unroll
        for (int j = 0; j < 5; j++)
            #pragma unroll
            for (int k = 0; k < 4; k++) acc[i][j][k] = 0.f;

    // ---- generic tile loader (A rows 0..255, B rows 256..335) ----
    #define LOAD_KB(KB, BUF)                                                        \
    do {                                                                            \
        const int k0_ = (KB) * BK;                                                  \
        const uint32_t st_ = sbase + (BUF) * STAGE;                                 \
        _Pragma("unroll")                                                           \
        for (int h = 0; h < NIT; h++) {                                             \
            int c_ = tid + h * 256;                                                 \
            if (NCH % 256 == 0 || c_ < NCH) {                                       \
                int row_ = c_ / CPR, q_ = c_ % CPR;                                 \
                if (row_ < MT_) {                                                   \
                    CP16(st_ + row_ * ROWB + q_ * 16,                               \
                         A + (size_t)(m0 + row_) * ldk + k0_ + q_ * 8);             \
                } else {                                                            \
                    int r2_ = row_ - MT_;                                           \
                    CP16(st_ + OFFB + r2_ * ROWB + q_ * 16,                         \
                         Bh + (size_t)(n0 + r2_) * ldk + k0_ + q_ * 8);             \
                }                                                                   \
            }                                                                       \
        }                                                                           \
    } while (0)

    LOAD_KB(0, 0);
    CP_COMMIT();

    for (int kb = 0; kb < NKB; kb++) {
        const int buf = kb & 1;
        if (kb + 1 < NKB) { LOAD_KB(kb + 1, buf ^ 1); CP_COMMIT(); CP_WAIT1(); }
        else              { CP_WAIT0(); }
        __syncthreads();

        const uint32_t st = sbase + buf * STAGE;
        #pragma unroll
        for (int ks = 0; ks < BK / 16; ks++) {
            const uint32_t ko = ks * 32;   // 16 fp16 = 32B
            uint32_t ah[4][4], bh[5][2];
            #pragma unroll
            for (int mi = 0; mi < 4; mi++) {
                uint32_t ad = st + aoff + mi * (16 * ROWB) + ko;
                LDSM_X4(ah[mi][0], ah[mi][1], ah[mi][2], ah[mi][3], ad);
            }
            #pragma unroll
            for (int nj = 0; nj < 2; nj++) {
                uint32_t bd = st + OFFB + boff4 + nj * (16 * ROWB) + ko;
                LDSM_X4(bh[nj*2][0], bh[nj*2][1], bh[nj*2+1][0], bh[nj*2+1][1], bd);
            }
            LDSM_X2(bh[4][0], bh[4][1], st + OFFB + boff2 + ko);

            #pragma unroll
            for (int mi = 0; mi < 4; mi++)
                #pragma unroll
                for (int ni = 0; ni < 5; ni++)
                    mma_fp16(acc[mi][ni], ah[mi][0], ah[mi][1], ah[mi][2], ah[mi][3],
                             bh[ni][0], bh[ni][1]);
        }
        __syncthreads();
    }
    #undef LOAD_KB

    // ---- epilogue (n always < 400: no N checks) ----
    if (!FUSE) {
        #pragma unroll
        for (int mi = 0; mi < 4; mi++) {
            int r = m0 + wm + mi * 16 + gr;
            #pragma unroll
            for (int ni = 0; ni < 5; ni++) {
                int n = n0 + wn + ni * 8 + gc * 2;
                float b0v = bias[n], b1v = bias[n + 1];
                #pragma unroll
                for (int half = 0; half < 2; half++) {
                    float x0 = fmaxf(acc[mi][ni][half * 2 + 0] + b0v, 0.f);
                    float x1 = fmaxf(acc[mi][ni][half * 2 + 1] + b1v, 0.f);
                    __half h0 = __float2half_rn(x0);
                    __half h1 = __float2half_rn(x1);
                    uint32_t ph = (uint32_t)__half_as_ushort(h0) |
                                  ((uint32_t)__half_as_ushort(h1) << 16);
                    size_t o = (size_t)(r + half * 8) * ldc + n;
                    *reinterpret_cast<uint32_t*>(C + o) = ph;
                }
            }
        }
    } else {
        #pragma unroll
        for (int mi = 0; mi < 4; mi++) {
            float s0 = 0.f, s1 = 0.f;
            #pragma unroll
            for (int ni = 0; ni < 5; ni++) {
                int n = n0 + wn + ni * 8 + gc * 2;
                float w0v = Wout[1 + n], w1v = Wout[2 + n];
                float b0v = bias[n],     b1v = bias[n + 1];
                s0 = fmaf(fmaxf(acc[mi][ni][0] + b0v, 0.f), w0v, s0);
                s0 = fmaf(fmaxf(acc[mi][ni][1] + b1v, 0.f), w1v, s0);
                s1 = fmaf(fmaxf(acc[mi][ni][2] + b0v, 0.f), w0v, s1);
                s1 = fmaf(fmaxf(acc[mi][ni][3] + b1v, 0.f), w1v, s1);
            }
            s0 += __shfl_xor_sync(0xffffffffu, s0, 1);
            s0 += __shfl_xor_sync(0xffffffffu, s0, 2);
            s1 += __shfl_xor_sync(0xffffffffu, s1, 1);
            s1 += __shfl_xor_sync(0xffffffffu, s1, 2);
            if (gc == 0) {
                part[wni][wm + mi * 16 + gr]     = s0;
                part[wni][wm + mi * 16 + gr + 8] = s1;
            }
        }
        __syncthreads();
        g_part[blockIdx.x][m0 + tid] = part[0][tid] + part[1][tid];
        __threadfence();
        __syncthreads();
        if (tid == 0) s_done = atomicAdd(&g_cnt[blockIdx.y], 1);
        __syncthreads();
        if (s_done == 4) {            // last CTA of this M-tile: finish
            __threadfence();
            int b = m0 + tid;
            float s = g_part[0][b] + g_part[1][b] + g_part[2][b] +
                      g_part[3][b] + g_part[4][b];
            out[b] = fmaf(g_fm[b], Wout[0], bout[0] + s);
            if (tid == 0) g_cnt[blockIdx.y] = 0;   // reset for next replay
        }
    }
}

// ============================================================================
// Launch
// ============================================================================
static void* sym_addr(const void* symbol) {
    void* p = nullptr;
    cudaGetSymbolAddress(&p, symbol);
    return p;
}

extern "C" void kernel_launch(void* const* d_in, const int* in_sizes, int n_in,
                              void* d_out, int out_size) {
    const float* cont    = (const float*)d_in[0];
    const int*   cat     = (const int*)  d_in[1];
    const float* w_cont  = (const float*)d_in[2];
    const float* b_cont  = (const float*)d_in[3];
    const float* t_first = (const float*)d_in[4];
    const float* t_emb   = (const float*)d_in[5];
    const float* W1      = (const float*)d_in[6];
    const float* b1      = (const float*)d_in[7];
    const float* W2      = (const float*)d_in[8];
    const float* b2      = (const float*)d_in[9];
    const float* Wout    = (const float*)d_in[10];
    const float* bout    = (const float*)d_in[11];
    float* out = (float*)d_out;

    const int SMEM1 = 2 * ((MT_ + NT_) * (2 * 64 + 16));   // 96768
    const int SMEM2 = 2 * ((MT_ + NT_) * (2 * 32 + 16));   // 53760
    cudaFuncSetAttribute((gemm_fp16<64, false>), cudaFuncAttributeMaxDynamicSharedMemorySize, SMEM1);
    cudaFuncSetAttribute((gemm_fp16<32, true>),  cudaFuncAttributeMaxDynamicSharedMemorySize, SMEM2);

    __half* dnn = (__half*)sym_addr(g_dnn);
    __half* h1  = (__half*)sym_addr(g_h1);
    __half* w1t = (__half*)sym_addr(g_w1t);
    __half* w2t = (__half*)sym_addr(g_w2t);

    // 1) gather + FM + weight prep (single launch)
    gather_prep_kernel<<<GATHER_BLKS + PREP_BLKS, 256>>>(
        cont, cat, w_cont, b_cont, t_first, t_emb, W1, W2);

    // 2) h1 = relu(dnn_in @ W1 + b1)     grid: 5 N-tiles x 64 M-tiles
    dim3 grid(5, B_ / MT_);
    gemm_fp16<64, false><<<grid, 256, SMEM1>>>(dnn, w1t, KP1_, KP1_ / 64,
                                               b1, nullptr, nullptr, nullptr, h1, KP2_);

    // 3) fused: h2 = relu(h1 @ W2 + b2); dot w/ Wout; last CTA writes out
    gemm_fp16<32, true><<<grid, 256, SMEM2>>>(h1, w2t, KP2_, KP2_ / 32,
                                              b2, Wout, bout, out, nullptr, 0);
}

// round 12
// speedup vs baseline: 1.2031x; 1.2031x over previous
#include <cuda_runtime.h>
#include <cuda_bf16.h>
#include <cuda_fp16.h>
#include <cstdint>

// ---------------- Problem constants ----------------
#define B_     16384
#define F_     26
#define V_     100000
#define E_     16
#define CONT_  13
#define K1_    429     // CONT_ + F_*E_
#define KP1_   448     // dnn_in K padded (mult of 64)
#define KP2_   416     // h1 K padded (mult of 32)
#define H_     400
#define NT_    80      // CTA N tile (5 * 80 = 400, exact)

// dnn_in layout (KP1_): [ emb 0..415 | cont 416..428 | zero 429..447 ]
// h1 layout (KP2_):     [ h1 0..399 | zero 400..415 ]  (pad never written)

// ---------------- Scratch (device globals) ----------------
__device__ __align__(256) __half g_dnn [(size_t)B_ * KP1_];
__device__ __align__(256) __half g_h1  [(size_t)B_ * KP2_];
__device__ __align__(256) __half g_w1t [(size_t)H_ * KP1_];
__device__ __align__(256) __half g_w2t [(size_t)H_ * KP2_];
__device__ float g_fm  [B_];
__device__ float g_part[5][B_];
__device__ int   g_cnt [B_ / 128];      // zero-init; self-resetting

// ---------------- PTX helpers ----------------
__device__ __forceinline__ uint32_t smem_u32(const void* p) {
    return (uint32_t)__cvta_generic_to_shared(p);
}
#define CP16(dst_u32, src) \
    asm volatile("cp.async.cg.shared.global [%0], [%1], 16;" :: "r"(dst_u32), "l"(src))
#define CP_COMMIT() asm volatile("cp.async.commit_group;" ::: "memory")
#define CP_WAIT0()  asm volatile("cp.async.wait_group 0;" ::: "memory")
#define CP_WAIT1()  asm volatile("cp.async.wait_group 1;" ::: "memory")

#define LDSM_X4(r0, r1, r2, r3, addr)                                          \
    asm volatile("ldmatrix.sync.aligned.m8n8.x4.shared.b16 {%0,%1,%2,%3},[%4];"\
                 : "=r"(r0), "=r"(r1), "=r"(r2), "=r"(r3) : "r"(addr))
#define LDSM_X2(r0, r1, addr)                                                  \
    asm volatile("ldmatrix.sync.aligned.m8n8.x2.shared.b16 {%0,%1},[%2];"      \
                 : "=r"(r0), "=r"(r1) : "r"(addr))

__device__ __forceinline__ void mma_fp16(float* c,
                                         uint32_t a0, uint32_t a1, uint32_t a2, uint32_t a3,
                                         uint32_t b0, uint32_t b1) {
    asm volatile(
        "mma.sync.aligned.m16n8k16.row.col.f32.f16.f16.f32 "
        "{%0,%1,%2,%3},{%4,%5,%6,%7},{%8,%9},{%0,%1,%2,%3};"
        : "+f"(c[0]), "+f"(c[1]), "+f"(c[2]), "+f"(c[3])
        : "r"(a0), "r"(a1), "r"(a2), "r"(a3), "r"(b0), "r"(b1));
}

// ============================================================================
// Kernel 1 (merged): blocks [0, 2048): gather + FM (one warp per sample);
//                    blocks [2048, 2748): weight prep.
// ============================================================================
#define GATHER_BLKS (B_ / 8)     // 2048
#define PREP_BLKS   700          // ceil(400*448 / 256)

__global__ void gather_prep_kernel(const float* __restrict__ cont,
                                   const int*   __restrict__ cat,
                                   const float* __restrict__ w_cont,
                                   const float* __restrict__ b_cont,
                                   const float* __restrict__ t_first,
                                   const float* __restrict__ t_emb,
                                   const float* __restrict__ W1,
                                   const float* __restrict__ W2) {
    if (blockIdx.x >= GATHER_BLKS) {
        int idx = (blockIdx.x - GATHER_BLKS) * 256 + threadIdx.x;
        if (idx < H_ * KP1_) {               // W1T: [400][448] in dnn layout
            int n = idx / KP1_, k = idx % KP1_;
            float v;
            if (k < 416)      v = W1[(size_t)(CONT_ + k) * H_ + n];
            else if (k < 429) v = W1[(size_t)(k - 416) * H_ + n];
            else              v = 0.f;
            g_w1t[idx] = __float2half_rn(v);
        }
        if (idx < H_ * KP2_) {               // W2T: [400][416]
            int n = idx / KP2_, k = idx % KP2_;
            float v = (k < H_) ? W2[(size_t)k * H_ + n] : 0.f;
            g_w2t[idx] = __float2half_rn(v);
        }
        return;
    }

    int warp = (blockIdx.x * blockDim.x + threadIdx.x) >> 5;
    int lane = threadIdx.x & 31;
    const int b = warp;

    float v[16];
    #pragma unroll
    for (int i = 0; i < 16; i++) v[i] = 0.f;
    float q = 0.f, scal = 0.f;

    if (lane < F_) {
        int idx = cat[b * F_ + lane];
        const float4* row =
            reinterpret_cast<const float4*>(t_emb + ((size_t)lane * V_ + (size_t)idx) * E_);
        float4 r0 = row[0], r1 = row[1], r2 = row[2], r3 = row[3];
        v[0]=r0.x; v[1]=r0.y; v[2]=r0.z; v[3]=r0.w;
        v[4]=r1.x; v[5]=r1.y; v[6]=r1.z; v[7]=r1.w;
        v[8]=r2.x; v[9]=r2.y; v[10]=r2.z; v[11]=r2.w;
        v[12]=r3.x; v[13]=r3.y; v[14]=r3.z; v[15]=r3.w;

        uint32_t pk[8];
        #pragma unroll
        for (int i = 0; i < 8; i++) {
            __half h0 = __float2half_rn(v[2*i]);
            __half h1 = __float2half_rn(v[2*i+1]);
            pk[i] = (uint32_t)__half_as_ushort(h0) | ((uint32_t)__half_as_ushort(h1) << 16);
            q = fmaf(v[2*i],   v[2*i],   q);
            q = fmaf(v[2*i+1], v[2*i+1], q);
        }
        uint4* dst = reinterpret_cast<uint4*>(g_dnn + (size_t)b * KP1_ + lane * E_);
        dst[0] = make_uint4(pk[0], pk[1], pk[2], pk[3]);
        dst[1] = make_uint4(pk[4], pk[5], pk[6], pk[7]);
        scal = t_first[(size_t)lane * V_ + (size_t)idx];
    }
    if (lane < CONT_) {
        float c = cont[b * CONT_ + lane];
        g_dnn[(size_t)b * KP1_ + 416 + lane] = __float2half_rn(c);
        scal = fmaf(c, w_cont[lane], scal);
    }
    if (lane < KP1_ - K1_) {     // zero cols 429..447 (19 lanes)
        g_dnn[(size_t)b * KP1_ + K1_ + lane] = __ushort_as_half((unsigned short)0);
    }

    #pragma unroll
    for (int off = 16; off; off >>= 1) {
        #pragma unroll
        for (int e = 0; e < 16; e++)
            v[e] += __shfl_xor_sync(0xffffffffu, v[e], off);
        q    += __shfl_xor_sync(0xffffffffu, q,    off);
        scal += __shfl_xor_sync(0xffffffffu, scal, off);
    }
    if (lane == 0) {
        float ss = 0.f;
        #pragma unroll
        for (int e = 0; e < 16; e++) ss = fmaf(v[e], v[e], ss);
        g_fm[b] = scal + b_cont[0] + 0.5f * (ss - q);
    }
}

// ============================================================================
// fp16 GEMM via mma.sync m16n8k16. CTA 128(M) x 80(N), 4 warps (2M x 2N),
//   warp tile 64x40, 128 threads. Template BK (32/64), double-buffered.
//   (R10 geometry — measured best; no occupancy constraint -> no spills.)
//   FUSE=0: relu(+bias) -> C fp16.
//   FUSE=1: fused dot w/ Wout -> g_part; last CTA per M-tile writes out.
// ============================================================================
template<int BK, bool FUSE>
__global__ void __launch_bounds__(128)
gemm_fp16(const __half* __restrict__ A,
          const __half* __restrict__ Bh,
          int ldk, int NKB,
          const float* __restrict__ bias,    // [H_]
          const float* __restrict__ Wout,    // [1+H_] (FUSE)
          const float* __restrict__ bout,    // [1]    (FUSE)
          float* __restrict__ out,           // [B_]   (FUSE)
          __half* __restrict__ C, int ldc) { // (!FUSE)
    constexpr int ROWB  = 2 * BK + 16;
    constexpr int CPR   = BK / 8;            // 16B chunks per row
    constexpr int OFFB  = 128 * ROWB;
    constexpr int STAGE = (128 + 80) * ROWB;
    constexpr int NCH   = 208 * CPR;         // chunks per stage
    constexpr int NIT   = (NCH + 127) / 128;

    extern __shared__ char smem_raw[];
    __shared__ float part[2][128];
    __shared__ int   s_done;
    const uint32_t sbase = smem_u32(smem_raw);

    const int tid  = threadIdx.x;
    const int warp = tid >> 5, lane = tid & 31;
    const int gr = lane >> 2, gc = lane & 3;
    const int wm  = (warp >> 1) * 64;    // warp row band (0 / 64)
    const int wni = warp & 1;
    const int wn  = wni * 40;            // warp col band (0 / 40)
    const int m0 = blockIdx.y * 128;
    const int n0 = blockIdx.x * NT_;

    const int lane8 = lane & 7;
    const int laneH = (lane >> 3) & 1;
    const int laneK = lane >> 4;
    const uint32_t aoff  = (uint32_t)((wm + lane8 + laneH * 8) * ROWB + laneK * 16);
    const uint32_t boff4 = (uint32_t)((wn + lane8 + laneK * 8) * ROWB + laneH * 16);
    const uint32_t boff2 = (uint32_t)((wn + 32 + lane8) * ROWB + laneH * 16);

    float acc[4][5][4];
    #pragma unroll
    for (int i = 0; i < 4; i++)
        #pragma unroll
        for (int j = 0; j < 5; j++)
            #pragma unroll
            for (int k = 0; k < 4; k++) acc[i][j][k] = 0.f;

    // ---- generic tile loader ----
    #define LOAD_KB(KB, BUF)                                                        \
    do {                                                                            \
        const int k0_ = (KB) * BK;                                                  \
        const uint32_t st_ = sbase + (BUF) * STAGE;                                 \
        _Pragma("unroll")                                                           \
        for (int h = 0; h < NIT; h++) {                                             \
            int c_ = tid + h * 128;                                                 \
            if (NCH % 128 == 0 || c_ < NCH) {                                       \
                int row_ = c_ / CPR, q_ = c_ % CPR;                                 \
                if (row_ < 128) {                                                   \
                    CP16(st_ + row_ * ROWB + q_ * 16,                               \
                         A + (size_t)(m0 + row_) * ldk + k0_ + q_ * 8);             \
                } else {                                                            \
                    int r2_ = row_ - 128;                                           \
                    CP16(st_ + OFFB + r2_ * ROWB + q_ * 16,                         \
                         Bh + (size_t)(n0 + r2_) * ldk + k0_ + q_ * 8);             \
                }                                                                   \
            }                                                                       \
        }                                                                           \
    } while (0)

    LOAD_KB(0, 0);
    CP_COMMIT();

    for (int kb = 0; kb < NKB; kb++) {
        const int buf = kb & 1;
        if (kb + 1 < NKB) { LOAD_KB(kb + 1, buf ^ 1); CP_COMMIT(); CP_WAIT1(); }
        else              { CP_WAIT0(); }
        __syncthreads();

        const uint32_t st = sbase + buf * STAGE;
        #pragma unroll
        for (int ks = 0; ks < BK / 16; ks++) {
            const uint32_t ko = ks * 32;   // 16 fp16 = 32B
            uint32_t ah[4][4], bh[5][2];
            #pragma unroll
            for (int mi = 0; mi < 4; mi++) {
                uint32_t ad = st + aoff + mi * (16 * ROWB) + ko;
                LDSM_X4(ah[mi][0], ah[mi][1], ah[mi][2], ah[mi][3], ad);
            }
            #pragma unroll
            for (int nj = 0; nj < 2; nj++) {
                uint32_t bd = st + OFFB + boff4 + nj * (16 * ROWB) + ko;
                LDSM_X4(bh[nj*2][0], bh[nj*2][1], bh[nj*2+1][0], bh[nj*2+1][1], bd);
            }
            LDSM_X2(bh[4][0], bh[4][1], st + OFFB + boff2 + ko);

            #pragma unroll
            for (int mi = 0; mi < 4; mi++)
                #pragma unroll
                for (int ni = 0; ni < 5; ni++)
                    mma_fp16(acc[mi][ni], ah[mi][0], ah[mi][1], ah[mi][2], ah[mi][3],
                             bh[ni][0], bh[ni][1]);
        }
        __syncthreads();
    }
    #undef LOAD_KB

    // ---- epilogue (n always < 400: no N checks) ----
    if (!FUSE) {
        #pragma unroll
        for (int mi = 0; mi < 4; mi++) {
            int r = m0 + wm + mi * 16 + gr;
            #pragma unroll
            for (int ni = 0; ni < 5; ni++) {
                int n = n0 + wn + ni * 8 + gc * 2;
                float b0v = bias[n], b1v = bias[n + 1];
                #pragma unroll
                for (int half = 0; half < 2; half++) {
                    float x0 = fmaxf(acc[mi][ni][half * 2 + 0] + b0v, 0.f);
                    float x1 = fmaxf(acc[mi][ni][half * 2 + 1] + b1v, 0.f);
                    __half h0 = __float2half_rn(x0);
                    __half h1 = __float2half_rn(x1);
                    uint32_t ph = (uint32_t)__half_as_ushort(h0) |
                                  ((uint32_t)__half_as_ushort(h1) << 16);
                    size_t o = (size_t)(r + half * 8) * ldc + n;
                    *reinterpret_cast<uint32_t*>(C + o) = ph;
                }
            }
        }
    } else {
        #pragma unroll
        for (int mi = 0; mi < 4; mi++) {
            float s0 = 0.f, s1 = 0.f;
            #pragma unroll
            for (int ni = 0; ni < 5; ni++) {
                int n = n0 + wn + ni * 8 + gc * 2;
                float w0v = Wout[1 + n], w1v = Wout[2 + n];
                float b0v = bias[n],     b1v = bias[n + 1];
                s0 = fmaf(fmaxf(acc[mi][ni][0] + b0v, 0.f), w0v, s0);
                s0 = fmaf(fmaxf(acc[mi][ni][1] + b1v, 0.f), w1v, s0);
                s1 = fmaf(fmaxf(acc[mi][ni][2] + b0v, 0.f), w0v, s1);
                s1 = fmaf(fmaxf(acc[mi][ni][3] + b1v, 0.f), w1v, s1);
            }
            s0 += __shfl_xor_sync(0xffffffffu, s0, 1);
            s0 += __shfl_xor_sync(0xffffffffu, s0, 2);
            s1 += __shfl_xor_sync(0xffffffffu, s1, 1);
            s1 += __shfl_xor_sync(0xffffffffu, s1, 2);
            if (gc == 0) {
                part[wni][wm + mi * 16 + gr]     = s0;
                part[wni][wm + mi * 16 + gr + 8] = s1;
            }
        }
        __syncthreads();
        g_part[blockIdx.x][m0 + tid] = part[0][tid] + part[1][tid];
        __threadfence();
        __syncthreads();
        if (tid == 0) s_done = atomicAdd(&g_cnt[blockIdx.y], 1);
        __syncthreads();
        if (s_done == 4) {            // last CTA of this M-tile: finish
            __threadfence();
            int b = m0 + tid;
            float s = g_part[0][b] + g_part[1][b] + g_part[2][b] +
                      g_part[3][b] + g_part[4][b];
            out[b] = fmaf(g_fm[b], Wout[0], bout[0] + s);
            if (tid == 0) g_cnt[blockIdx.y] = 0;   // reset for next replay
        }
    }
}

// ============================================================================
// Launch
// ============================================================================
static void* sym_addr(const void* symbol) {
    void* p = nullptr;
    cudaGetSymbolAddress(&p, symbol);
    return p;
}

extern "C" void kernel_launch(void* const* d_in, const int* in_sizes, int n_in,
                              void* d_out, int out_size) {
    const float* cont    = (const float*)d_in[0];
    const int*   cat     = (const int*)  d_in[1];
    const float* w_cont  = (const float*)d_in[2];
    const float* b_cont  = (const float*)d_in[3];
    const float* t_first = (const float*)d_in[4];
    const float* t_emb   = (const float*)d_in[5];
    const float* W1      = (const float*)d_in[6];
    const float* b1      = (const float*)d_in[7];
    const float* W2      = (const float*)d_in[8];
    const float* b2      = (const float*)d_in[9];
    const float* Wout    = (const float*)d_in[10];
    const float* bout    = (const float*)d_in[11];
    float* out = (float*)d_out;

    const int SMEM1 = 2 * (208 * (2 * 64 + 16));   // BK=64: 59904
    const int SMEM2 = 2 * (208 * (2 * 32 + 16));   // BK=32: 33280
    cudaFuncSetAttribute((gemm_fp16<64, false>), cudaFuncAttributeMaxDynamicSharedMemorySize, SMEM1);
    cudaFuncSetAttribute((gemm_fp16<32, true>),  cudaFuncAttributeMaxDynamicSharedMemorySize, SMEM2);

    __half* dnn = (__half*)sym_addr(g_dnn);
    __half* h1  = (__half*)sym_addr(g_h1);
    __half* w1t = (__half*)sym_addr(g_w1t);
    __half* w2t = (__half*)sym_addr(g_w2t);

    // 1) gather + FM + weight prep (single launch)
    gather_prep_kernel<<<GATHER_BLKS + PREP_BLKS, 256>>>(
        cont, cat, w_cont, b_cont, t_first, t_emb, W1, W2);

    // 2) h1 = relu(dnn_in @ W1 + b1)     grid: 5 N-tiles x 128 M-tiles
    dim3 grid(5, B_ / 128);
    gemm_fp16<64, false><<<grid, 128, SMEM1>>>(dnn, w1t, KP1_, KP1_ / 64,
                                               b1, nullptr, nullptr, nullptr, h1, KP2_);

    // 3) fused: h2 = relu(h1 @ W2 + b2); dot w/ Wout; last CTA writes out
    gemm_fp16<32, true><<<grid, 128, SMEM2>>>(h1, w2t, KP2_, KP2_ / 32,
                                              b2, Wout, bout, out, nullptr, 0);
}